// round 13
// baseline (speedup 1.0000x reference)
#include <cuda_runtime.h>
#include <cuda_fp16.h>
#include <cstdint>

#define SEQ 512
#define BATCH 256
#define EMB 300
#define HID 10
#define G3 30
#define CHUNK 32
#define NCH 16
#define NKT 19                  // k-tiles of 16: covers k 0..303

// SMEM layout (bytes)
#define X32_OFF  0
#define X32_SLOT 38400          // 32 rows x 300 fp32; slots: (bt*2 + parity)
#define A_STRIDE 656            // 328 halves/row (304 used + pad), LDSM-friendly
#define A_SLOT   (32 * A_STRIDE)              // 20992; one per bt
#define A_OFF    (4 * X32_SLOT)               // 153600
// gi tile TRANSPOSED: [gate 0..31][step 0..31], stride 36 floats (16B-aligned)
#define GIT_STRIDE 36
#define GI_SLOT  (32 * GIT_STRIDE * 4)        // 4608
#define GI_OFF   (A_OFF + 2 * A_SLOT)         // 195584
#define SMEM_B   (GI_OFF + 4 * GI_SLOT)       // 214016

// W_ih_f pre-packed as mma.sync B-fragments: [nh][kt][nt][j][lane]
__device__ uint32_t g_bf[2 * NKT * 2 * 2 * 32];

// ---------- helpers ----------
__device__ __forceinline__ float tanha(float x) {
    float y;
    asm("tanh.approx.f32 %0, %1;" : "=f"(y) : "f"(x));
    return y;
}
__device__ __forceinline__ float sig_full(float x) {
    return fmaf(tanha(0.5f * x), 0.5f, 0.5f);
}
__device__ __forceinline__ uint32_t s2u(const void* p) {
    uint32_t a;
    asm("{ .reg .u64 t; cvta.to.shared.u64 t, %1; cvt.u32.u64 %0, t; }"
        : "=r"(a) : "l"(p));
    return a;
}
__device__ __forceinline__ unsigned long long pk2(float lo, float hi) {
    unsigned long long r;
    asm("mov.b64 %0, {%1, %2};" : "=l"(r) : "f"(lo), "f"(hi));
    return r;
}
__device__ __forceinline__ void upk2(unsigned long long v, float& lo, float& hi) {
    asm("mov.b64 {%0, %1}, %2;" : "=f"(lo), "=f"(hi) : "l"(v));
}
__device__ __forceinline__ unsigned long long fma2(unsigned long long a,
                                                   unsigned long long b,
                                                   unsigned long long c) {
    unsigned long long d;
    asm("fma.rn.f32x2 %0, %1, %2, %3;" : "=l"(d) : "l"(a), "l"(b), "l"(c));
    return d;
}
__device__ __forceinline__ unsigned long long add2(unsigned long long a,
                                                   unsigned long long b) {
    unsigned long long d;
    asm("add.rn.f32x2 %0, %1, %2;" : "=l"(d) : "l"(a), "l"(b));
    return d;
}
__device__ __forceinline__ float getc(float4 v, int i) {
    return i == 0 ? v.x : i == 1 ? v.y : i == 2 ? v.z : v.w;
}
__device__ __forceinline__ void cpa16(uint32_t dst, const void* src) {
    asm volatile("cp.async.cg.shared.global [%0], [%1], 16;"
                 :: "r"(dst), "l"(src) : "memory");
}
__device__ __forceinline__ void cpa_commit() {
    asm volatile("cp.async.commit_group;" ::: "memory");
}
__device__ __forceinline__ void cpa_wait1() {
    asm volatile("cp.async.wait_group 1;" ::: "memory");
}
__device__ __forceinline__ void cpa_wait0() {
    asm volatile("cp.async.wait_group 0;" ::: "memory");
}
__device__ __forceinline__ void ldsm4(uint32_t& a0, uint32_t& a1,
                                      uint32_t& a2, uint32_t& a3, uint32_t addr) {
    asm volatile("ldmatrix.sync.aligned.m8n8.x4.shared.b16 {%0,%1,%2,%3}, [%4];"
                 : "=r"(a0), "=r"(a1), "=r"(a2), "=r"(a3) : "r"(addr));
}
__device__ __forceinline__ void mma16816(float* d, uint32_t a0, uint32_t a1,
                                         uint32_t a2, uint32_t a3,
                                         uint32_t b0, uint32_t b1) {
    asm volatile(
        "mma.sync.aligned.m16n8k16.row.col.f32.f16.f16.f32 "
        "{%0,%1,%2,%3}, {%4,%5,%6,%7}, {%8,%9}, {%0,%1,%2,%3};"
        : "+f"(d[0]), "+f"(d[1]), "+f"(d[2]), "+f"(d[3])
        : "r"(a0), "r"(a1), "r"(a2), "r"(a3), "r"(b0), "r"(b1));
}

// ---------- prep: W_ih_f -> fp16 B fragments (rows<20 pre-scaled 0.5) -------
__global__ void k_prepB(const float* __restrict__ w) {
    int i = blockIdx.x * 256 + threadIdx.x;
    if (i >= 2 * NKT * 2 * 2 * 32) return;
    int lane = i & 31;
    int t = i >> 5;
    int j  = t & 1;  t >>= 1;
    int nt = t & 1;  t >>= 1;
    int kt = t % NKT;
    int nh = t / NKT;
    int n = nh * 16 + nt * 8 + (lane >> 2);
    int k = kt * 16 + (lane & 3) * 2 + j * 8;
    float sc = (n < 20) ? 0.5f : 1.0f;
    float w0 = (n < G3 && k < EMB)     ? sc * w[n * EMB + k]     : 0.0f;
    float w1 = (n < G3 && k + 1 < EMB) ? sc * w[n * EMB + k + 1] : 0.0f;
    __half2 h = __floats2half2_rn(w0, w1);
    g_bf[i] = *(uint32_t*)&h;
}

// ---------- fused kernel: 192 threads (6 warps), 1 block = 2 batches -------
// wid 0,1: producers bt0 | wid 4,5: producers bt1
// wid 2: rec bt0 | wid 3: rec bt1  (each rec warp alone on SMSP 2 / 3)
__global__ void __launch_bounds__(192, 1) k_fused(
    const float* __restrict__ x,
    const float* __restrict__ b_ihf,
    const float* __restrict__ w_ihb, const float* __restrict__ b_ihb,
    const float* __restrict__ whh,  const float* __restrict__ bhhf,
    const float* __restrict__ bhhb, const float* __restrict__ wlin,
    const float* __restrict__ blin, float* __restrict__ out)
{
    extern __shared__ char smc[];
    const uint32_t sbase = s2u(smc);
    const int tid  = threadIdx.x;
    const int wid  = tid >> 5;
    const int lane = tid & 31;
    const int b0   = blockIdx.x * 2;
    const unsigned mfull = 0xffffffffu;

    const bool is_rec = (wid == 2) || (wid == 3);
    const int bt = is_rec ? (wid - 2) : ((wid >= 4) ? 1 : 0);
    const int nh = wid & 1;

    // zero A slots once (pad cols 300-327 must stay 0; convert rewrites 0-299)
    {
        uint4 z = make_uint4(0, 0, 0, 0);
        uint4* sA = (uint4*)(smc + A_OFF);
        for (int i = tid; i < (2 * A_SLOT) / 16; i += 192) sA[i] = z;
    }

    // ---- producer setup: persistent B fragments + prologue cp.async ----
    uint32_t bf[NKT][2][2];
    if (!is_rec) {
        const uint32_t* gB = g_bf + nh * (NKT * 2 * 2 * 32);
#pragma unroll
        for (int kt = 0; kt < NKT; ++kt)
#pragma unroll
            for (int nt = 0; nt < 2; ++nt)
#pragma unroll
                for (int j = 0; j < 2; ++j)
                    bf[kt][nt][j] =
                        __ldg(gB + ((kt * 2 + nt) * 2 + j) * 32 + lane);

        const float4* src = (const float4*)(x +
            ((size_t)(b0 + bt) * SEQ + nh * 16) * EMB);
        uint32_t dst = sbase + X32_OFF + (bt * 2 + 0) * X32_SLOT + nh * 16 * 1200;
        for (int i = lane; i < 1200; i += 32) cpa16(dst + i * 16, src + i);
        cpa_commit();
    }

    // ---- rec setup: per-j f32x2 gate rows + biases + bwd-dir gi dot ----
    const int l   = lane;
    const int l30 = (l < G3) ? l : 0;
    const int j10 = (l < HID) ? l : 0;
    float gb = 0.0f;
    unsigned long long wr2[5], wz2[5], wn2[5], hbnp = 0ULL;
    float cbr = 0.0f, cbz = 0.0f, bin_ = 0.0f;
    float hj = 0.0f;

    if (is_rec) {
        const int b = b0 + bt;
        const float4* xq = (const float4*)(x + ((size_t)b * SEQ + SEQ - 1) * EMB);
        const float4* wq = (const float4*)(w_ihb + (size_t)l30 * EMB);
        float a0 = 0, a1 = 0, a2 = 0, a3 = 0;
#pragma unroll 5
        for (int k4 = 0; k4 < EMB / 4; ++k4) {
            float4 xv = __ldg(xq + k4);
            float4 wv4 = __ldg(wq + k4);
            a0 = fmaf(xv.x, wv4.x, a0);
            a1 = fmaf(xv.y, wv4.y, a1);
            a2 = fmaf(xv.z, wv4.z, a2);
            a3 = fmaf(xv.w, wv4.w, a3);
        }
        gb = (a0 + a1) + (a2 + a3) + ((l < G3) ? __ldg(b_ihb + l) : 0.0f);

#pragma unroll
        for (int k = 0; k < 5; ++k) { wr2[k] = 0; wz2[k] = 0; wn2[k] = 0; }
        if (l < HID) {
#pragma unroll
            for (int k = 0; k < 5; ++k) {
                wr2[k] = pk2(0.5f * __ldg(whh + l * HID + 2 * k),
                             0.5f * __ldg(whh + l * HID + 2 * k + 1));
                wz2[k] = pk2(0.5f * __ldg(whh + (l + 10) * HID + 2 * k),
                             0.5f * __ldg(whh + (l + 10) * HID + 2 * k + 1));
                wn2[k] = pk2(0.5f * __ldg(whh + (l + 20) * HID + 2 * k),
                             0.5f * __ldg(whh + (l + 20) * HID + 2 * k + 1));
            }
            cbr  = 0.5f * (__ldg(b_ihf + l)      + __ldg(bhhf + l));
            cbz  = 0.5f * (__ldg(b_ihf + l + 10) + __ldg(bhhf + l + 10));
            bin_ = __ldg(b_ihf + l + 20);
            hbnp = pk2(0.5f * __ldg(bhhf + l + 20), 0.0f);
        }
    }

    __syncthreads();

    // ---- lockstep: cpasync(p+1) | convert(p)+HMMA(p) | consume(p-1) ----
    for (int p = 0; p <= NCH; ++p) {
        if (!is_rec) {
            if (p + 1 < NCH) {
                const float4* src = (const float4*)(x +
                    ((size_t)(b0 + bt) * SEQ + (size_t)(p + 1) * CHUNK + nh * 16) * EMB);
                uint32_t dst = sbase + X32_OFF
                    + (bt * 2 + ((p + 1) & 1)) * X32_SLOT + nh * 16 * 1200;
                for (int i = lane; i < 1200; i += 32) cpa16(dst + i * 16, src + i);
                cpa_commit();
            }

            if (p < NCH) {
                if (p + 1 < NCH) cpa_wait1(); else cpa_wait0();

                const float4* xs = (const float4*)(smc + X32_OFF
                    + (bt * 2 + (p & 1)) * X32_SLOT + nh * 16 * 1200);
                char* aslot = smc + A_OFF + bt * A_SLOT;
#pragma unroll 4
                for (int i = lane; i < 16 * 75; i += 32) {
                    int row = i / 75, q = i - row * 75;
                    float4 v = xs[i];
                    __half2 h0 = __floats2half2_rn(v.x, v.y);
                    __half2 h1 = __floats2half2_rn(v.z, v.w);
                    *(uint2*)(aslot + (nh * 16 + row) * A_STRIDE + q * 8) =
                        make_uint2(*(uint32_t*)&h0, *(uint32_t*)&h1);
                }

                asm volatile("bar.sync %0, 64;" :: "r"(1 + bt) : "memory");

                const uint32_t abase = sbase + A_OFF + bt * A_SLOT;
                float* gis = (float*)(smc + GI_OFF + (bt * 2 + (p & 1)) * GI_SLOT);
                const int mi = lane >> 3, r = lane & 7;

                float d[2][2][4];
#pragma unroll
                for (int mt = 0; mt < 2; ++mt)
#pragma unroll
                    for (int nt = 0; nt < 2; ++nt)
#pragma unroll
                        for (int e = 0; e < 4; ++e) d[mt][nt][e] = 0.0f;

#pragma unroll
                for (int kt = 0; kt < NKT; ++kt) {
#pragma unroll
                    for (int mt = 0; mt < 2; ++mt) {
                        uint32_t addr = abase
                            + (mt * 16 + (mi & 1) * 8 + r) * A_STRIDE
                            + (mi >> 1) * 16 + kt * 32;
                        uint32_t a0, a1, a2, a3;
                        ldsm4(a0, a1, a2, a3, addr);
                        mma16816(d[mt][0], a0, a1, a2, a3,
                                 bf[kt][0][0], bf[kt][0][1]);
                        mma16816(d[mt][1], a0, a1, a2, a3,
                                 bf[kt][1][0], bf[kt][1][1]);
                    }
                }

                // TRANSPOSED store: gi[gate][step], stride 36 floats
                const int rq = lane >> 2, cq = (lane & 3) * 2;
#pragma unroll
                for (int mt = 0; mt < 2; ++mt)
#pragma unroll
                    for (int nt = 0; nt < 2; ++nt) {
                        int col = nh * 16 + nt * 8 + cq;   // gate
                        int row = mt * 16 + rq;            // step
                        gis[col * GIT_STRIDE + row]           = d[mt][nt][0];
                        gis[(col + 1) * GIT_STRIDE + row]     = d[mt][nt][1];
                        gis[col * GIT_STRIDE + row + 8]       = d[mt][nt][2];
                        gis[(col + 1) * GIT_STRIDE + row + 8] = d[mt][nt][3];
                    }
            }
        }

        // consumer: chunk p-1, per-j, quad-loaded transposed gi
        if (is_rec && p >= 1) {
            const int c = p - 1;
            const float* gis =
                (const float*)(smc + GI_OFF + (bt * 2 + (c & 1)) * GI_SLOT);
            const float4* rq4 = (const float4*)(gis + j10 * GIT_STRIDE);
            const float4* zq4 = (const float4*)(gis + (j10 + 10) * GIT_STRIDE);
            const float4* nq4 = (const float4*)(gis + (j10 + 20) * GIT_STRIDE);

            float4 r4 = rq4[0], z4 = zq4[0], n4 = nq4[0];
#pragma unroll 1
            for (int q = 0; q < 8; ++q) {
                int qn = (q + 1) & 7;
                float4 r4n = rq4[qn], z4n = zq4[qn], n4n = nq4[qn];
#pragma unroll
                for (int u = 0; u < 4; ++u) {
                    float grp = getc(r4, u) + cbr;
                    float gzp = getc(z4, u) + cbz;
                    float gnp = getc(n4, u) + bin_;

                    unsigned long long h2[5];
#pragma unroll
                    for (int k = 0; k < 5; ++k) {
                        float lo = __shfl_sync(mfull, hj, 2 * k);
                        float hi = __shfl_sync(mfull, hj, 2 * k + 1);
                        h2[k] = pk2(lo, hi);
                    }

                    unsigned long long aR = fma2(h2[0], wr2[0], pk2(grp, 0.0f));
                    unsigned long long bR = fma2(h2[1], wr2[1], 0ULL);
                    unsigned long long aZ = fma2(h2[0], wz2[0], pk2(gzp, 0.0f));
                    unsigned long long bZ = fma2(h2[1], wz2[1], 0ULL);
                    unsigned long long aN = fma2(h2[0], wn2[0], hbnp);
                    unsigned long long bN = fma2(h2[1], wn2[1], 0ULL);
                    aR = fma2(h2[2], wr2[2], aR);  bR = fma2(h2[3], wr2[3], bR);
                    aZ = fma2(h2[2], wz2[2], aZ);  bZ = fma2(h2[3], wz2[3], bZ);
                    aN = fma2(h2[2], wn2[2], aN);  bN = fma2(h2[3], wn2[3], bN);
                    aR = fma2(h2[4], wr2[4], aR);
                    aZ = fma2(h2[4], wz2[4], aZ);
                    aN = fma2(h2[4], wn2[4], aN);

                    float x0, x1;
                    upk2(add2(aR, bR), x0, x1);
                    float ar = x0 + x1;
                    upk2(add2(aZ, bZ), x0, x1);
                    float az = x0 + x1;
                    upk2(add2(aN, bN), x0, x1);
                    float ah = x0 + x1;

                    float tr = tanha(ar);
                    float tz = tanha(az);
                    float base = gnp + ah;
                    float nn = tanha(fmaf(ah, tr, base));
                    float z  = fmaf(tz, 0.5f, 0.5f);
                    hj = fmaf(z, hj - nn, nn);
                }
                r4 = r4n; z4 = z4n; n4 = n4n;
            }
        }

        __syncthreads();
    }

    // ---- epilogue: backward single step + linear head ----
    if (is_rec) {
        float bb  = (l < G3) ? __ldg(bhhb + l) : 0.0f;
        float sb  = gb + bb;
        float azb = __shfl_sync(mfull, sb, l + 10);
        float gbn = __shfl_sync(mfull, gb, l + 20);
        float bbn = __shfl_sync(mfull, bb, l + 20);
        float rb  = sig_full(sb);
        float zb  = sig_full(azb);
        float nb  = tanha(fmaf(rb, bbn, gbn));
        float hbv = (1.0f - zb) * nb;

        float cacc = 0.0f;
        if (l < HID) cacc = __ldg(wlin + l) * hj + __ldg(wlin + HID + l) * hbv;
        cacc += __shfl_down_sync(mfull, cacc, 8);
        cacc += __shfl_down_sync(mfull, cacc, 4);
        cacc += __shfl_down_sync(mfull, cacc, 2);
        cacc += __shfl_down_sync(mfull, cacc, 1);
        if (l == 0) out[b0 + bt] = cacc + __ldg(blin);
    }
}

extern "C" void kernel_launch(void* const* d_in, const int* in_sizes, int n_in,
                              void* d_out, int out_size)
{
    const float* x      = (const float*)d_in[0];
    const float* w_ih_f = (const float*)d_in[1];
    const float* w_hh_f = (const float*)d_in[2];
    const float* b_ih_f = (const float*)d_in[3];
    const float* b_hh_f = (const float*)d_in[4];
    const float* w_ih_b = (const float*)d_in[5];
    /* w_hh_b (d_in[6]) mathematically unused: h0 = 0 for the single bwd step */
    const float* b_ih_b = (const float*)d_in[7];
    const float* b_hh_b = (const float*)d_in[8];
    const float* w_lin  = (const float*)d_in[9];
    const float* b_lin  = (const float*)d_in[10];
    float* out = (float*)d_out;

    k_prepB<<<(2 * NKT * 2 * 2 * 32 + 255) / 256, 256>>>(w_ih_f);

    cudaFuncSetAttribute(k_fused, cudaFuncAttributeMaxDynamicSharedMemorySize,
                         SMEM_B);
    k_fused<<<BATCH / 2, 192, SMEM_B>>>(x, b_ih_f, w_ih_b, b_ih_b,
                                        w_hh_f, b_hh_f, b_hh_b, w_lin, b_lin,
                                        out);
}

// round 14
// speedup vs baseline: 1.0320x; 1.0320x over previous
#include <cuda_runtime.h>
#include <cuda_fp16.h>
#include <cstdint>

#define SEQ 512
#define BATCH 256
#define EMB 300
#define HID 10
#define G3 30
#define CHUNK 32
#define NCH 16
#define NKT 19                  // k-tiles of 16: covers k 0..303

// SMEM layout (bytes)
#define X32_OFF  0
#define X32_SLOT 38400          // 32 rows x 300 fp32; slots: (bt*2 + parity)
#define A_STRIDE 656            // 328 halves/row (304 used + pad), LDSM-friendly
#define A_SLOT   (32 * A_STRIDE)              // 20992; one per bt
#define A_OFF    (4 * X32_SLOT)               // 153600
// gi tile TRANSPOSED: [gate 0..31][step 0..31], stride 36 floats (16B-aligned)
#define GIT_STRIDE 36
#define GI_SLOT  (32 * GIT_STRIDE * 4)        // 4608
#define GI_OFF   (A_OFF + 2 * A_SLOT)         // 195584
#define SMEM_B   (GI_OFF + 4 * GI_SLOT)       // 214016

// W_ih_f pre-packed as mma.sync B-fragments: [nh][kt][nt][j][lane]
__device__ uint32_t g_bf[2 * NKT * 2 * 2 * 32];

// ---------- helpers ----------
__device__ __forceinline__ float tanha(float x) {
    float y;
    asm("tanh.approx.f32 %0, %1;" : "=f"(y) : "f"(x));
    return y;
}
__device__ __forceinline__ float sig_full(float x) {
    return fmaf(tanha(0.5f * x), 0.5f, 0.5f);
}
__device__ __forceinline__ uint32_t s2u(const void* p) {
    uint32_t a;
    asm("{ .reg .u64 t; cvta.to.shared.u64 t, %1; cvt.u32.u64 %0, t; }"
        : "=r"(a) : "l"(p));
    return a;
}
__device__ __forceinline__ unsigned long long pk2(float lo, float hi) {
    unsigned long long r;
    asm("mov.b64 %0, {%1, %2};" : "=l"(r) : "f"(lo), "f"(hi));
    return r;
}
__device__ __forceinline__ void upk2(unsigned long long v, float& lo, float& hi) {
    asm("mov.b64 {%0, %1}, %2;" : "=f"(lo), "=f"(hi) : "l"(v));
}
__device__ __forceinline__ unsigned long long fma2(unsigned long long a,
                                                   unsigned long long b,
                                                   unsigned long long c) {
    unsigned long long d;
    asm("fma.rn.f32x2 %0, %1, %2, %3;" : "=l"(d) : "l"(a), "l"(b), "l"(c));
    return d;
}
__device__ __forceinline__ unsigned long long add2(unsigned long long a,
                                                   unsigned long long b) {
    unsigned long long d;
    asm("add.rn.f32x2 %0, %1, %2;" : "=l"(d) : "l"(a), "l"(b));
    return d;
}
__device__ __forceinline__ float getc(float4 v, int i) {
    return i == 0 ? v.x : i == 1 ? v.y : i == 2 ? v.z : v.w;
}
__device__ __forceinline__ void cpa16(uint32_t dst, const void* src) {
    asm volatile("cp.async.cg.shared.global [%0], [%1], 16;"
                 :: "r"(dst), "l"(src) : "memory");
}
__device__ __forceinline__ void cpa_commit() {
    asm volatile("cp.async.commit_group;" ::: "memory");
}
__device__ __forceinline__ void cpa_wait1() {
    asm volatile("cp.async.wait_group 1;" ::: "memory");
}
__device__ __forceinline__ void cpa_wait0() {
    asm volatile("cp.async.wait_group 0;" ::: "memory");
}
__device__ __forceinline__ void ldsm4(uint32_t& a0, uint32_t& a1,
                                      uint32_t& a2, uint32_t& a3, uint32_t addr) {
    asm volatile("ldmatrix.sync.aligned.m8n8.x4.shared.b16 {%0,%1,%2,%3}, [%4];"
                 : "=r"(a0), "=r"(a1), "=r"(a2), "=r"(a3) : "r"(addr));
}
__device__ __forceinline__ void mma16816(float* d, uint32_t a0, uint32_t a1,
                                         uint32_t a2, uint32_t a3,
                                         uint32_t b0, uint32_t b1) {
    asm volatile(
        "mma.sync.aligned.m16n8k16.row.col.f32.f16.f16.f32 "
        "{%0,%1,%2,%3}, {%4,%5,%6,%7}, {%8,%9}, {%0,%1,%2,%3};"
        : "+f"(d[0]), "+f"(d[1]), "+f"(d[2]), "+f"(d[3])
        : "r"(a0), "r"(a1), "r"(a2), "r"(a3), "r"(b0), "r"(b1));
}

// ---------- prep: W_ih_f -> fp16 B fragments (rows<20 pre-scaled 0.5) -------
__global__ void k_prepB(const float* __restrict__ w) {
    int i = blockIdx.x * 256 + threadIdx.x;
    if (i >= 2 * NKT * 2 * 2 * 32) return;
    int lane = i & 31;
    int t = i >> 5;
    int j  = t & 1;  t >>= 1;
    int nt = t & 1;  t >>= 1;
    int kt = t % NKT;
    int nh = t / NKT;
    int n = nh * 16 + nt * 8 + (lane >> 2);
    int k = kt * 16 + (lane & 3) * 2 + j * 8;
    float sc = (n < 20) ? 0.5f : 1.0f;
    float w0 = (n < G3 && k < EMB)     ? sc * w[n * EMB + k]     : 0.0f;
    float w1 = (n < G3 && k + 1 < EMB) ? sc * w[n * EMB + k + 1] : 0.0f;
    __half2 h = __floats2half2_rn(w0, w1);
    g_bf[i] = *(uint32_t*)&h;
}

// ---------- fused kernel: 192 threads (6 warps), 1 block = 2 batches -------
// wid 0,1: producers bt0 | wid 4,5: producers bt1
// wid 2: rec bt0 | wid 3: rec bt1  (each rec warp alone on SMSP 2 / 3)
// Rec scheme: lane g<30 owns gate-row g's dot; finalize happens in lane j<10.
__global__ void __launch_bounds__(192, 1) k_fused(
    const float* __restrict__ x,
    const float* __restrict__ b_ihf,
    const float* __restrict__ w_ihb, const float* __restrict__ b_ihb,
    const float* __restrict__ whh,  const float* __restrict__ bhhf,
    const float* __restrict__ bhhb, const float* __restrict__ wlin,
    const float* __restrict__ blin, float* __restrict__ out)
{
    extern __shared__ char smc[];
    const uint32_t sbase = s2u(smc);
    const int tid  = threadIdx.x;
    const int wid  = tid >> 5;
    const int lane = tid & 31;
    const int b0   = blockIdx.x * 2;
    const unsigned mfull = 0xffffffffu;

    const bool is_rec = (wid == 2) || (wid == 3);
    const int bt = is_rec ? (wid - 2) : ((wid >= 4) ? 1 : 0);
    const int nh = wid & 1;

    // zero A slots once (pad cols 300-327 must stay 0; convert rewrites 0-299)
    {
        uint4 z = make_uint4(0, 0, 0, 0);
        uint4* sA = (uint4*)(smc + A_OFF);
        for (int i = tid; i < (2 * A_SLOT) / 16; i += 192) sA[i] = z;
    }

    // ---- producer setup: persistent B fragments + prologue cp.async ----
    uint32_t bf[NKT][2][2];
    if (!is_rec) {
        const uint32_t* gB = g_bf + nh * (NKT * 2 * 2 * 32);
#pragma unroll
        for (int kt = 0; kt < NKT; ++kt)
#pragma unroll
            for (int nt = 0; nt < 2; ++nt)
#pragma unroll
                for (int j = 0; j < 2; ++j)
                    bf[kt][nt][j] =
                        __ldg(gB + ((kt * 2 + nt) * 2 + j) * 32 + lane);

        const float4* src = (const float4*)(x +
            ((size_t)(b0 + bt) * SEQ + nh * 16) * EMB);
        uint32_t dst = sbase + X32_OFF + (bt * 2 + 0) * X32_SLOT + nh * 16 * 1200;
        for (int i = lane; i < 1200; i += 32) cpa16(dst + i * 16, src + i);
        cpa_commit();
    }

    // ---- rec setup: per-gate dot rows + folded biases + bwd-dir gi dot ----
    const int l   = lane;
    const int l30 = (l < G3) ? l : 0;
    float gb = 0.0f;
    unsigned long long wg2[5];
    float cbase = 0.0f, gsel = 0.0f, bin_ = 0.0f;
    float hj = 0.0f;

    if (is_rec) {
        const int b = b0 + bt;
        const float4* xq = (const float4*)(x + ((size_t)b * SEQ + SEQ - 1) * EMB);
        const float4* wq = (const float4*)(w_ihb + (size_t)l30 * EMB);
        float a0 = 0, a1 = 0, a2 = 0, a3 = 0;
#pragma unroll 5
        for (int k4 = 0; k4 < EMB / 4; ++k4) {
            float4 xv = __ldg(xq + k4);
            float4 wv4 = __ldg(wq + k4);
            a0 = fmaf(xv.x, wv4.x, a0);
            a1 = fmaf(xv.y, wv4.y, a1);
            a2 = fmaf(xv.z, wv4.z, a2);
            a3 = fmaf(xv.w, wv4.w, a3);
        }
        gb = (a0 + a1) + (a2 + a3) + ((l < G3) ? __ldg(b_ihb + l) : 0.0f);

#pragma unroll
        for (int k = 0; k < 5; ++k) wg2[k] = 0ULL;
        if (l < G3) {
            // ALL gate rows pre-scaled by 0.5 (r,z: sigmoid trick; n: r*X = ah + ah*tr)
#pragma unroll
            for (int k = 0; k < 5; ++k)
                wg2[k] = pk2(0.5f * __ldg(whh + l * HID + 2 * k),
                             0.5f * __ldg(whh + l * HID + 2 * k + 1));
            if (l < 20) {
                cbase = 0.5f * (__ldg(b_ihf + l) + __ldg(bhhf + l));
                gsel  = 1.0f;
            } else {
                cbase = 0.5f * __ldg(bhhf + l);   // n-gate: hidden bias only
                bin_  = __ldg(b_ihf + l);         // input bias joins gnp
            }
        }
    }

    __syncthreads();

    // ---- lockstep: cpasync(p+1) | convert(p)+HMMA(p) | consume(p-1) ----
    for (int p = 0; p <= NCH; ++p) {
        if (!is_rec) {
            if (p + 1 < NCH) {
                const float4* src = (const float4*)(x +
                    ((size_t)(b0 + bt) * SEQ + (size_t)(p + 1) * CHUNK + nh * 16) * EMB);
                uint32_t dst = sbase + X32_OFF
                    + (bt * 2 + ((p + 1) & 1)) * X32_SLOT + nh * 16 * 1200;
                for (int i = lane; i < 1200; i += 32) cpa16(dst + i * 16, src + i);
                cpa_commit();
            }

            if (p < NCH) {
                if (p + 1 < NCH) cpa_wait1(); else cpa_wait0();

                const float4* xs = (const float4*)(smc + X32_OFF
                    + (bt * 2 + (p & 1)) * X32_SLOT + nh * 16 * 1200);
                char* aslot = smc + A_OFF + bt * A_SLOT;
#pragma unroll 4
                for (int i = lane; i < 16 * 75; i += 32) {
                    int row = i / 75, q = i - row * 75;
                    float4 v = xs[i];
                    __half2 h0 = __floats2half2_rn(v.x, v.y);
                    __half2 h1 = __floats2half2_rn(v.z, v.w);
                    *(uint2*)(aslot + (nh * 16 + row) * A_STRIDE + q * 8) =
                        make_uint2(*(uint32_t*)&h0, *(uint32_t*)&h1);
                }

                asm volatile("bar.sync %0, 64;" :: "r"(1 + bt) : "memory");

                const uint32_t abase = sbase + A_OFF + bt * A_SLOT;
                float* gis = (float*)(smc + GI_OFF + (bt * 2 + (p & 1)) * GI_SLOT);
                const int mi = lane >> 3, r = lane & 7;

                float d[2][2][4];
#pragma unroll
                for (int mt = 0; mt < 2; ++mt)
#pragma unroll
                    for (int nt = 0; nt < 2; ++nt)
#pragma unroll
                        for (int e = 0; e < 4; ++e) d[mt][nt][e] = 0.0f;

#pragma unroll
                for (int kt = 0; kt < NKT; ++kt) {
#pragma unroll
                    for (int mt = 0; mt < 2; ++mt) {
                        uint32_t addr = abase
                            + (mt * 16 + (mi & 1) * 8 + r) * A_STRIDE
                            + (mi >> 1) * 16 + kt * 32;
                        uint32_t a0, a1, a2, a3;
                        ldsm4(a0, a1, a2, a3, addr);
                        mma16816(d[mt][0], a0, a1, a2, a3,
                                 bf[kt][0][0], bf[kt][0][1]);
                        mma16816(d[mt][1], a0, a1, a2, a3,
                                 bf[kt][1][0], bf[kt][1][1]);
                    }
                }

                // TRANSPOSED store: gi[gate][step], stride 36 floats
                const int rq = lane >> 2, cq = (lane & 3) * 2;
#pragma unroll
                for (int mt = 0; mt < 2; ++mt)
#pragma unroll
                    for (int nt = 0; nt < 2; ++nt) {
                        int col = nh * 16 + nt * 8 + cq;   // gate
                        int row = mt * 16 + rq;            // step
                        gis[col * GIT_STRIDE + row]           = d[mt][nt][0];
                        gis[(col + 1) * GIT_STRIDE + row]     = d[mt][nt][1];
                        gis[col * GIT_STRIDE + row + 8]       = d[mt][nt][2];
                        gis[(col + 1) * GIT_STRIDE + row + 8] = d[mt][nt][3];
                    }
            }
        }

        // consumer: chunk p-1 — hybrid scheme, 1 LDS.128 / lane / 4 steps
        if (is_rec && p >= 1) {
            const int c = p - 1;
            const float* gis =
                (const float*)(smc + GI_OFF + (bt * 2 + (c & 1)) * GI_SLOT);
            const float4* gq4 = (const float4*)(gis + l30 * GIT_STRIDE);

            float4 g4 = gq4[0];
#pragma unroll 1
            for (int q = 0; q < 8; ++q) {
                float4 g4n = gq4[(q + 1) & 7];
#pragma unroll
                for (int u = 0; u < 4; ++u) {
                    // broadcast h first (longest latency)
                    unsigned long long h2[5];
#pragma unroll
                    for (int k = 0; k < 5; ++k) {
                        float lo = __shfl_sync(mfull, hj, 2 * k);
                        float hi = __shfl_sync(mfull, hj, 2 * k + 1);
                        h2[k] = pk2(lo, hi);
                    }

                    // independent gi/bias work fills the shfl shadow
                    float gval = getc(g4, u);
                    float ainit = fmaf(gsel, gval, cbase);
                    float gnp = gval + bin_;

                    // single 10-dot for THIS lane's gate row
                    unsigned long long c0 = fma2(h2[0], wg2[0], pk2(ainit, 0.0f));
                    unsigned long long c1 = fma2(h2[1], wg2[1], 0ULL);
                    c0 = fma2(h2[2], wg2[2], c0);
                    c1 = fma2(h2[3], wg2[3], c1);
                    c0 = fma2(h2[4], wg2[4], c0);
                    float x0, x1;
                    upk2(add2(c0, c1), x0, x1);
                    float a = x0 + x1;         // r,z: 0.5*preact | n: 0.5*(Wn h + bhn)

                    float t = tanha(a);        // tr at lane j, tz at j+10
                    float base = gnp + a;      // n-gate: gn + bin + ah'

                    float zsh = __shfl_sync(mfull, t, l + 10);
                    float ash = __shfl_sync(mfull, a, l + 20);
                    float bsh = __shfl_sync(mfull, base, l + 20);

                    float z  = fmaf(zsh, 0.5f, 0.5f);
                    float nn = tanha(fmaf(ash, t, bsh));
                    hj = fmaf(z, hj - nn, nn);
                }
                g4 = g4n;
            }
        }

        __syncthreads();
    }

    // ---- epilogue: backward single step + linear head ----
    if (is_rec) {
        float bb  = (l < G3) ? __ldg(bhhb + l) : 0.0f;
        float sb  = gb + bb;
        float azb = __shfl_sync(mfull, sb, l + 10);
        float gbn = __shfl_sync(mfull, gb, l + 20);
        float bbn = __shfl_sync(mfull, bb, l + 20);
        float rb  = sig_full(sb);
        float zb  = sig_full(azb);
        float nb  = tanha(fmaf(rb, bbn, gbn));
        float hbv = (1.0f - zb) * nb;

        float cacc = 0.0f;
        if (l < HID) cacc = __ldg(wlin + l) * hj + __ldg(wlin + HID + l) * hbv;
        cacc += __shfl_down_sync(mfull, cacc, 8);
        cacc += __shfl_down_sync(mfull, cacc, 4);
        cacc += __shfl_down_sync(mfull, cacc, 2);
        cacc += __shfl_down_sync(mfull, cacc, 1);
        if (l == 0) out[b0 + bt] = cacc + __ldg(blin);
    }
}

extern "C" void kernel_launch(void* const* d_in, const int* in_sizes, int n_in,
                              void* d_out, int out_size)
{
    const float* x      = (const float*)d_in[0];
    const float* w_ih_f = (const float*)d_in[1];
    const float* w_hh_f = (const float*)d_in[2];
    const float* b_ih_f = (const float*)d_in[3];
    const float* b_hh_f = (const float*)d_in[4];
    const float* w_ih_b = (const float*)d_in[5];
    /* w_hh_b (d_in[6]) mathematically unused: h0 = 0 for the single bwd step */
    const float* b_ih_b = (const float*)d_in[7];
    const float* b_hh_b = (const float*)d_in[8];
    const float* w_lin  = (const float*)d_in[9];
    const float* b_lin  = (const float*)d_in[10];
    float* out = (float*)d_out;

    k_prepB<<<(2 * NKT * 2 * 2 * 32 + 255) / 256, 256>>>(w_ih_f);

    cudaFuncSetAttribute(k_fused, cudaFuncAttributeMaxDynamicSharedMemorySize,
                         SMEM_B);
    k_fused<<<BATCH / 2, 192, SMEM_B>>>(x, b_ih_f, w_ih_b, b_ih_b,
                                        w_hh_f, b_hh_f, b_hh_b, w_lin, b_lin,
                                        out);
}

// round 15
// speedup vs baseline: 1.0910x; 1.0571x over previous
#include <cuda_runtime.h>
#include <cuda_fp16.h>
#include <cstdint>

#define SEQ 512
#define BATCH 256
#define EMB 300
#define HID 10
#define G3 30
#define CHUNK 32
#define NCH 16
#define NKT 19                  // k-tiles of 16: covers k 0..303

// SMEM layout (bytes)
#define X32_OFF  0
#define X32_SLOT 38400          // 32 rows x 300 fp32; slots: (bt*2 + parity)
#define A_STRIDE 656            // 328 halves/row (304 used + pad), LDSM-friendly
#define A_SLOT   (32 * A_STRIDE)              // 20992; one per bt
#define A_OFF    (4 * X32_SLOT)               // 153600
// gi tile TRANSPOSED: [gate 0..31][step 0..31], stride 36 floats (16B-aligned)
#define GIT_STRIDE 36
#define GI_SLOT  (32 * GIT_STRIDE * 4)        // 4608
#define GI_OFF   (A_OFF + 2 * A_SLOT)         // 195584
// h state: per bt, 2 buffers x 16 floats (double-buffered by step parity)
#define HB_OFF   (GI_OFF + 4 * GI_SLOT)       // 214016
#define SMEM_B   (HB_OFF + 256)               // 214272

// W_ih_f pre-packed as mma.sync B-fragments: [nh][kt][nt][j][lane]
__device__ uint32_t g_bf[2 * NKT * 2 * 2 * 32];

// ---------- helpers ----------
__device__ __forceinline__ float tanha(float x) {
    float y;
    asm("tanh.approx.f32 %0, %1;" : "=f"(y) : "f"(x));
    return y;
}
__device__ __forceinline__ float sig_full(float x) {
    return fmaf(tanha(0.5f * x), 0.5f, 0.5f);
}
__device__ __forceinline__ uint32_t s2u(const void* p) {
    uint32_t a;
    asm("{ .reg .u64 t; cvta.to.shared.u64 t, %1; cvt.u32.u64 %0, t; }"
        : "=r"(a) : "l"(p));
    return a;
}
__device__ __forceinline__ unsigned long long pk2(float lo, float hi) {
    unsigned long long r;
    asm("mov.b64 %0, {%1, %2};" : "=l"(r) : "f"(lo), "f"(hi));
    return r;
}
__device__ __forceinline__ void upk2(unsigned long long v, float& lo, float& hi) {
    asm("mov.b64 {%0, %1}, %2;" : "=f"(lo), "=f"(hi) : "l"(v));
}
__device__ __forceinline__ unsigned long long fma2(unsigned long long a,
                                                   unsigned long long b,
                                                   unsigned long long c) {
    unsigned long long d;
    asm("fma.rn.f32x2 %0, %1, %2, %3;" : "=l"(d) : "l"(a), "l"(b), "l"(c));
    return d;
}
__device__ __forceinline__ unsigned long long add2(unsigned long long a,
                                                   unsigned long long b) {
    unsigned long long d;
    asm("add.rn.f32x2 %0, %1, %2;" : "=l"(d) : "l"(a), "l"(b));
    return d;
}
__device__ __forceinline__ float getc(float4 v, int i) {
    return i == 0 ? v.x : i == 1 ? v.y : i == 2 ? v.z : v.w;
}
__device__ __forceinline__ void cpa16(uint32_t dst, const void* src) {
    asm volatile("cp.async.cg.shared.global [%0], [%1], 16;"
                 :: "r"(dst), "l"(src) : "memory");
}
__device__ __forceinline__ void cpa_commit() {
    asm volatile("cp.async.commit_group;" ::: "memory");
}
__device__ __forceinline__ void cpa_wait1() {
    asm volatile("cp.async.wait_group 1;" ::: "memory");
}
__device__ __forceinline__ void cpa_wait0() {
    asm volatile("cp.async.wait_group 0;" ::: "memory");
}
__device__ __forceinline__ void ldsm4(uint32_t& a0, uint32_t& a1,
                                      uint32_t& a2, uint32_t& a3, uint32_t addr) {
    asm volatile("ldmatrix.sync.aligned.m8n8.x4.shared.b16 {%0,%1,%2,%3}, [%4];"
                 : "=r"(a0), "=r"(a1), "=r"(a2), "=r"(a3) : "r"(addr));
}
__device__ __forceinline__ void mma16816(float* d, uint32_t a0, uint32_t a1,
                                         uint32_t a2, uint32_t a3,
                                         uint32_t b0, uint32_t b1) {
    asm volatile(
        "mma.sync.aligned.m16n8k16.row.col.f32.f16.f16.f32 "
        "{%0,%1,%2,%3}, {%4,%5,%6,%7}, {%8,%9}, {%0,%1,%2,%3};"
        : "+f"(d[0]), "+f"(d[1]), "+f"(d[2]), "+f"(d[3])
        : "r"(a0), "r"(a1), "r"(a2), "r"(a3), "r"(b0), "r"(b1));
}

// ---------- prep: W_ih_f -> fp16 B fragments (rows<20 pre-scaled 0.5) -------
__global__ void k_prepB(const float* __restrict__ w) {
    int i = blockIdx.x * 256 + threadIdx.x;
    if (i >= 2 * NKT * 2 * 2 * 32) return;
    int lane = i & 31;
    int t = i >> 5;
    int j  = t & 1;  t >>= 1;
    int nt = t & 1;  t >>= 1;
    int kt = t % NKT;
    int nh = t / NKT;
    int n = nh * 16 + nt * 8 + (lane >> 2);
    int k = kt * 16 + (lane & 3) * 2 + j * 8;
    float sc = (n < 20) ? 0.5f : 1.0f;
    float w0 = (n < G3 && k < EMB)     ? sc * w[n * EMB + k]     : 0.0f;
    float w1 = (n < G3 && k + 1 < EMB) ? sc * w[n * EMB + k + 1] : 0.0f;
    __half2 h = __floats2half2_rn(w0, w1);
    g_bf[i] = *(uint32_t*)&h;
}

// ---------- fused kernel: 192 threads (6 warps), 1 block = 2 batches -------
// wid 0,1: producers bt0 | wid 4,5: producers bt1
// wid 2: rec bt0 | wid 3: rec bt1  (each rec warp alone on SMSP 2 / 3)
// Rec: per-j, h broadcast via double-buffered SMEM (no shfl in steady state)
__global__ void __launch_bounds__(192, 1) k_fused(
    const float* __restrict__ x,
    const float* __restrict__ b_ihf,
    const float* __restrict__ w_ihb, const float* __restrict__ b_ihb,
    const float* __restrict__ whh,  const float* __restrict__ bhhf,
    const float* __restrict__ bhhb, const float* __restrict__ wlin,
    const float* __restrict__ blin, float* __restrict__ out)
{
    extern __shared__ char smc[];
    const uint32_t sbase = s2u(smc);
    const int tid  = threadIdx.x;
    const int wid  = tid >> 5;
    const int lane = tid & 31;
    const int b0   = blockIdx.x * 2;
    const unsigned mfull = 0xffffffffu;

    const bool is_rec = (wid == 2) || (wid == 3);
    const int bt = is_rec ? (wid - 2) : ((wid >= 4) ? 1 : 0);
    const int nh = wid & 1;

    // zero A slots + h buffers once
    {
        uint4 z = make_uint4(0, 0, 0, 0);
        uint4* sA = (uint4*)(smc + A_OFF);
        for (int i = tid; i < (2 * A_SLOT) / 16; i += 192) sA[i] = z;
        if (tid < 16) ((uint4*)(smc + HB_OFF))[tid] = z;   // 256 B of h state
    }

    // ---- producer setup: persistent B fragments + prologue cp.async ----
    uint32_t bf[NKT][2][2];
    if (!is_rec) {
        const uint32_t* gB = g_bf + nh * (NKT * 2 * 2 * 32);
#pragma unroll
        for (int kt = 0; kt < NKT; ++kt)
#pragma unroll
            for (int nt = 0; nt < 2; ++nt)
#pragma unroll
                for (int j = 0; j < 2; ++j)
                    bf[kt][nt][j] =
                        __ldg(gB + ((kt * 2 + nt) * 2 + j) * 32 + lane);

        const float4* src = (const float4*)(x +
            ((size_t)(b0 + bt) * SEQ + nh * 16) * EMB);
        uint32_t dst = sbase + X32_OFF + (bt * 2 + 0) * X32_SLOT + nh * 16 * 1200;
        for (int i = lane; i < 1200; i += 32) cpa16(dst + i * 16, src + i);
        cpa_commit();
    }

    // ---- rec setup: per-j f32x2 gate rows + biases + bwd-dir gi dot ----
    const int l   = lane;
    const int l30 = (l < G3) ? l : 0;
    const int j10 = (l < HID) ? l : 0;
    float gb = 0.0f;
    unsigned long long wr2[5], wz2[5], wn2[5], hbnp = 0ULL;
    float cbr = 0.0f, cbz = 0.0f, bin_ = 0.0f;
    float hj = 0.0f;

    if (is_rec) {
        const int b = b0 + bt;
        const float4* xq = (const float4*)(x + ((size_t)b * SEQ + SEQ - 1) * EMB);
        const float4* wq = (const float4*)(w_ihb + (size_t)l30 * EMB);
        float a0 = 0, a1 = 0, a2 = 0, a3 = 0;
#pragma unroll 5
        for (int k4 = 0; k4 < EMB / 4; ++k4) {
            float4 xv = __ldg(xq + k4);
            float4 wv4 = __ldg(wq + k4);
            a0 = fmaf(xv.x, wv4.x, a0);
            a1 = fmaf(xv.y, wv4.y, a1);
            a2 = fmaf(xv.z, wv4.z, a2);
            a3 = fmaf(xv.w, wv4.w, a3);
        }
        gb = (a0 + a1) + (a2 + a3) + ((l < G3) ? __ldg(b_ihb + l) : 0.0f);

#pragma unroll
        for (int k = 0; k < 5; ++k) { wr2[k] = 0; wz2[k] = 0; wn2[k] = 0; }
        if (l < HID) {
#pragma unroll
            for (int k = 0; k < 5; ++k) {
                wr2[k] = pk2(0.5f * __ldg(whh + l * HID + 2 * k),
                             0.5f * __ldg(whh + l * HID + 2 * k + 1));
                wz2[k] = pk2(0.5f * __ldg(whh + (l + 10) * HID + 2 * k),
                             0.5f * __ldg(whh + (l + 10) * HID + 2 * k + 1));
                wn2[k] = pk2(0.5f * __ldg(whh + (l + 20) * HID + 2 * k),
                             0.5f * __ldg(whh + (l + 20) * HID + 2 * k + 1));
            }
            cbr  = 0.5f * (__ldg(b_ihf + l)      + __ldg(bhhf + l));
            cbz  = 0.5f * (__ldg(b_ihf + l + 10) + __ldg(bhhf + l + 10));
            bin_ = __ldg(b_ihf + l + 20);
            hbnp = pk2(0.5f * __ldg(bhhf + l + 20), 0.0f);
        }
    }

    __syncthreads();

    // ---- lockstep: cpasync(p+1) | convert(p)+HMMA(p) | consume(p-1) ----
    for (int p = 0; p <= NCH; ++p) {
        if (!is_rec) {
            if (p + 1 < NCH) {
                const float4* src = (const float4*)(x +
                    ((size_t)(b0 + bt) * SEQ + (size_t)(p + 1) * CHUNK + nh * 16) * EMB);
                uint32_t dst = sbase + X32_OFF
                    + (bt * 2 + ((p + 1) & 1)) * X32_SLOT + nh * 16 * 1200;
                for (int i = lane; i < 1200; i += 32) cpa16(dst + i * 16, src + i);
                cpa_commit();
            }

            if (p < NCH) {
                if (p + 1 < NCH) cpa_wait1(); else cpa_wait0();

                const float4* xs = (const float4*)(smc + X32_OFF
                    + (bt * 2 + (p & 1)) * X32_SLOT + nh * 16 * 1200);
                char* aslot = smc + A_OFF + bt * A_SLOT;
#pragma unroll 4
                for (int i = lane; i < 16 * 75; i += 32) {
                    int row = i / 75, q = i - row * 75;
                    float4 v = xs[i];
                    __half2 h0 = __floats2half2_rn(v.x, v.y);
                    __half2 h1 = __floats2half2_rn(v.z, v.w);
                    *(uint2*)(aslot + (nh * 16 + row) * A_STRIDE + q * 8) =
                        make_uint2(*(uint32_t*)&h0, *(uint32_t*)&h1);
                }

                asm volatile("bar.sync %0, 64;" :: "r"(1 + bt) : "memory");

                const uint32_t abase = sbase + A_OFF + bt * A_SLOT;
                float* gis = (float*)(smc + GI_OFF + (bt * 2 + (p & 1)) * GI_SLOT);
                const int mi = lane >> 3, r = lane & 7;

                float d[2][2][4];
#pragma unroll
                for (int mt = 0; mt < 2; ++mt)
#pragma unroll
                    for (int nt = 0; nt < 2; ++nt)
#pragma unroll
                        for (int e = 0; e < 4; ++e) d[mt][nt][e] = 0.0f;

#pragma unroll
                for (int kt = 0; kt < NKT; ++kt) {
#pragma unroll
                    for (int mt = 0; mt < 2; ++mt) {
                        uint32_t addr = abase
                            + (mt * 16 + (mi & 1) * 8 + r) * A_STRIDE
                            + (mi >> 1) * 16 + kt * 32;
                        uint32_t a0, a1, a2, a3;
                        ldsm4(a0, a1, a2, a3, addr);
                        mma16816(d[mt][0], a0, a1, a2, a3,
                                 bf[kt][0][0], bf[kt][0][1]);
                        mma16816(d[mt][1], a0, a1, a2, a3,
                                 bf[kt][1][0], bf[kt][1][1]);
                    }
                }

                // TRANSPOSED store: gi[gate][step], stride 36 floats
                const int rq = lane >> 2, cq = (lane & 3) * 2;
#pragma unroll
                for (int mt = 0; mt < 2; ++mt)
#pragma unroll
                    for (int nt = 0; nt < 2; ++nt) {
                        int col = nh * 16 + nt * 8 + cq;   // gate
                        int row = mt * 16 + rq;            // step
                        gis[col * GIT_STRIDE + row]           = d[mt][nt][0];
                        gis[(col + 1) * GIT_STRIDE + row]     = d[mt][nt][1];
                        gis[col * GIT_STRIDE + row + 8]       = d[mt][nt][2];
                        gis[(col + 1) * GIT_STRIDE + row + 8] = d[mt][nt][3];
                    }
            }
        }

        // consumer: chunk p-1 — per-j, SMEM-h double buffer, no shuffles
        if (is_rec && p >= 1) {
            const int c = p - 1;
            const float* gis =
                (const float*)(smc + GI_OFF + (bt * 2 + (c & 1)) * GI_SLOT);
            const float4* rq4 = (const float4*)(gis + j10 * GIT_STRIDE);
            const float4* zq4 = (const float4*)(gis + (j10 + 10) * GIT_STRIDE);
            const float4* nq4 = (const float4*)(gis + (j10 + 20) * GIT_STRIDE);
            char* hbb = smc + HB_OFF + bt * 128;

            float4 r4 = rq4[0], z4 = zq4[0], n4 = nq4[0];
#pragma unroll 1
            for (int q = 0; q < 8; ++q) {
                int qn = (q + 1) & 7;
                float4 r4n = rq4[qn], z4n = zq4[qn], n4n = nq4[qn];
#pragma unroll
                for (int u4 = 0; u4 < 4; ++u4) {
                    const int par = u4 & 1;   // chunk is 32 steps: parity = u4&1

                    // read h (broadcast LDS, directly paired for fma2)
                    const ulonglong2* hb = (const ulonglong2*)(hbb + par * 64);
                    ulonglong2 hA = hb[0];                         // h0..h3
                    ulonglong2 hB = hb[1];                         // h4..h7
                    unsigned long long h4 =
                        ((const unsigned long long*)hb)[2 * 2];    // h8,h9

                    float grp = getc(r4, u4) + cbr;
                    float gzp = getc(z4, u4) + cbz;
                    float gnp = getc(n4, u4) + bin_;

                    unsigned long long aR = fma2(hA.x, wr2[0], pk2(grp, 0.0f));
                    unsigned long long bR = fma2(hA.y, wr2[1], 0ULL);
                    unsigned long long aZ = fma2(hA.x, wz2[0], pk2(gzp, 0.0f));
                    unsigned long long bZ = fma2(hA.y, wz2[1], 0ULL);
                    unsigned long long aN = fma2(hA.x, wn2[0], hbnp);
                    unsigned long long bN = fma2(hA.y, wn2[1], 0ULL);
                    aR = fma2(hB.x, wr2[2], aR);  bR = fma2(hB.y, wr2[3], bR);
                    aZ = fma2(hB.x, wz2[2], aZ);  bZ = fma2(hB.y, wz2[3], bZ);
                    aN = fma2(hB.x, wn2[2], aN);  bN = fma2(hB.y, wn2[3], bN);
                    aR = fma2(h4, wr2[4], aR);
                    aZ = fma2(h4, wz2[4], aZ);
                    aN = fma2(h4, wn2[4], aN);

                    float x0, x1;
                    upk2(add2(aR, bR), x0, x1);
                    float ar = x0 + x1;
                    upk2(add2(aZ, bZ), x0, x1);
                    float az = x0 + x1;
                    upk2(add2(aN, bN), x0, x1);
                    float ah = x0 + x1;

                    float tr = tanha(ar);
                    float tz = tanha(az);
                    float nn = tanha(fmaf(ah, tr, gnp + ah));
                    float z  = fmaf(tz, 0.5f, 0.5f);
                    hj = fmaf(z, hj - nn, nn);

                    // write next h (predicated, no divergence cost)
                    if (l < HID)
                        *(float*)(hbb + (par ^ 1) * 64 + l * 4) = hj;
                    __syncwarp();
                }
                r4 = r4n; z4 = z4n; n4 = n4n;
            }
        }

        __syncthreads();
    }

    // ---- epilogue: backward single step + linear head ----
    if (is_rec) {
        float bb  = (l < G3) ? __ldg(bhhb + l) : 0.0f;
        float sb  = gb + bb;
        float azb = __shfl_sync(mfull, sb, l + 10);
        float gbn = __shfl_sync(mfull, gb, l + 20);
        float bbn = __shfl_sync(mfull, bb, l + 20);
        float rb  = sig_full(sb);
        float zb  = sig_full(azb);
        float nb  = tanha(fmaf(rb, bbn, gbn));
        float hbv = (1.0f - zb) * nb;

        float cacc = 0.0f;
        if (l < HID) cacc = __ldg(wlin + l) * hj + __ldg(wlin + HID + l) * hbv;
        cacc += __shfl_down_sync(mfull, cacc, 8);
        cacc += __shfl_down_sync(mfull, cacc, 4);
        cacc += __shfl_down_sync(mfull, cacc, 2);
        cacc += __shfl_down_sync(mfull, cacc, 1);
        if (l == 0) out[b0 + bt] = cacc + __ldg(blin);
    }
}

extern "C" void kernel_launch(void* const* d_in, const int* in_sizes, int n_in,
                              void* d_out, int out_size)
{
    const float* x      = (const float*)d_in[0];
    const float* w_ih_f = (const float*)d_in[1];
    const float* w_hh_f = (const float*)d_in[2];
    const float* b_ih_f = (const float*)d_in[3];
    const float* b_hh_f = (const float*)d_in[4];
    const float* w_ih_b = (const float*)d_in[5];
    /* w_hh_b (d_in[6]) mathematically unused: h0 = 0 for the single bwd step */
    const float* b_ih_b = (const float*)d_in[7];
    const float* b_hh_b = (const float*)d_in[8];
    const float* w_lin  = (const float*)d_in[9];
    const float* b_lin  = (const float*)d_in[10];
    float* out = (float*)d_out;

    k_prepB<<<(2 * NKT * 2 * 2 * 32 + 255) / 256, 256>>>(w_ih_f);

    cudaFuncSetAttribute(k_fused, cudaFuncAttributeMaxDynamicSharedMemorySize,
                         SMEM_B);
    k_fused<<<BATCH / 2, 192, SMEM_B>>>(x, b_ih_f, w_ih_b, b_ih_b,
                                        w_hh_f, b_hh_f, b_hh_b, w_lin, b_lin,
                                        out);
}

// round 16
// speedup vs baseline: 1.1020x; 1.0101x over previous
#include <cuda_runtime.h>
#include <cuda_fp16.h>
#include <cstdint>

#define SEQ 512
#define BATCH 256
#define EMB 300
#define HID 10
#define G3 30
#define CHUNK 32
#define NCH 16
#define NKT 19                  // k-tiles of 16: covers k 0..303

// SMEM layout (bytes)
#define X32_OFF  0
#define X32_SLOT 38400          // 32 rows x 300 fp32; slots: (bt*2 + parity)
#define A_STRIDE 656            // 328 halves/row (304 used + pad), LDSM-friendly
#define A_SLOT   (32 * A_STRIDE)              // 20992; one per bt
#define A_OFF    (4 * X32_SLOT)               // 153600
// gi tile TRANSPOSED: [gate 0..31][step 0..31], stride 36 floats (16B-aligned)
#define GIT_STRIDE 36
#define GI_SLOT  (32 * GIT_STRIDE * 4)        // 4608
#define GI_OFF   (A_OFF + 2 * A_SLOT)         // 195584
// h state: per bt, 2 buffers x 16 floats (double-buffered by step parity)
#define HB_OFF   (GI_OFF + 4 * GI_SLOT)       // 214016
#define SMEM_B   (HB_OFF + 256)               // 214272

// ---------- helpers ----------
__device__ __forceinline__ float tanha(float x) {
    float y;
    asm("tanh.approx.f32 %0, %1;" : "=f"(y) : "f"(x));
    return y;
}
__device__ __forceinline__ float sig_full(float x) {
    return fmaf(tanha(0.5f * x), 0.5f, 0.5f);
}
__device__ __forceinline__ uint32_t s2u(const void* p) {
    uint32_t a;
    asm("{ .reg .u64 t; cvta.to.shared.u64 t, %1; cvt.u32.u64 %0, t; }"
        : "=r"(a) : "l"(p));
    return a;
}
__device__ __forceinline__ unsigned long long pk2(float lo, float hi) {
    unsigned long long r;
    asm("mov.b64 %0, {%1, %2};" : "=l"(r) : "f"(lo), "f"(hi));
    return r;
}
__device__ __forceinline__ void upk2(unsigned long long v, float& lo, float& hi) {
    asm("mov.b64 {%0, %1}, %2;" : "=f"(lo), "=f"(hi) : "l"(v));
}
__device__ __forceinline__ unsigned long long fma2(unsigned long long a,
                                                   unsigned long long b,
                                                   unsigned long long c) {
    unsigned long long d;
    asm("fma.rn.f32x2 %0, %1, %2, %3;" : "=l"(d) : "l"(a), "l"(b), "l"(c));
    return d;
}
__device__ __forceinline__ unsigned long long add2(unsigned long long a,
                                                   unsigned long long b) {
    unsigned long long d;
    asm("add.rn.f32x2 %0, %1, %2;" : "=l"(d) : "l"(a), "l"(b));
    return d;
}
__device__ __forceinline__ float getc(float4 v, int i) {
    return i == 0 ? v.x : i == 1 ? v.y : i == 2 ? v.z : v.w;
}
__device__ __forceinline__ void cpa16(uint32_t dst, const void* src) {
    asm volatile("cp.async.cg.shared.global [%0], [%1], 16;"
                 :: "r"(dst), "l"(src) : "memory");
}
__device__ __forceinline__ void cpa_commit() {
    asm volatile("cp.async.commit_group;" ::: "memory");
}
__device__ __forceinline__ void cpa_wait1() {
    asm volatile("cp.async.wait_group 1;" ::: "memory");
}
__device__ __forceinline__ void cpa_wait0() {
    asm volatile("cp.async.wait_group 0;" ::: "memory");
}
__device__ __forceinline__ void ldsm4(uint32_t& a0, uint32_t& a1,
                                      uint32_t& a2, uint32_t& a3, uint32_t addr) {
    asm volatile("ldmatrix.sync.aligned.m8n8.x4.shared.b16 {%0,%1,%2,%3}, [%4];"
                 : "=r"(a0), "=r"(a1), "=r"(a2), "=r"(a3) : "r"(addr));
}
__device__ __forceinline__ void mma16816(float* d, uint32_t a0, uint32_t a1,
                                         uint32_t a2, uint32_t a3,
                                         uint32_t b0, uint32_t b1) {
    asm volatile(
        "mma.sync.aligned.m16n8k16.row.col.f32.f16.f16.f32 "
        "{%0,%1,%2,%3}, {%4,%5,%6,%7}, {%8,%9}, {%0,%1,%2,%3};"
        : "+f"(d[0]), "+f"(d[1]), "+f"(d[2]), "+f"(d[3])
        : "r"(a0), "r"(a1), "r"(a2), "r"(a3), "r"(b0), "r"(b1));
}

// ---------- fused kernel: 192 threads (6 warps), 1 block = 2 batches -------
// wid 0,1: producers bt0 | wid 4,5: producers bt1
// wid 2: rec bt0 | wid 3: rec bt1  (each rec warp alone on SMSP 2 / 3)
// Rec: per-j, SMEM-h double buffer, no syncwarp (in-order warp STS->LDS)
__global__ void __launch_bounds__(192, 1) k_fused(
    const float* __restrict__ x,
    const float* __restrict__ w_ihf, const float* __restrict__ b_ihf,
    const float* __restrict__ w_ihb, const float* __restrict__ b_ihb,
    const float* __restrict__ whh,  const float* __restrict__ bhhf,
    const float* __restrict__ bhhb, const float* __restrict__ wlin,
    const float* __restrict__ blin, float* __restrict__ out)
{
    extern __shared__ char smc[];
    const uint32_t sbase = s2u(smc);
    const int tid  = threadIdx.x;
    const int wid  = tid >> 5;
    const int lane = tid & 31;
    const int b0   = blockIdx.x * 2;
    const unsigned mfull = 0xffffffffu;

    const bool is_rec = (wid == 2) || (wid == 3);
    const int bt = is_rec ? (wid - 2) : ((wid >= 4) ? 1 : 0);
    const int nh = wid & 1;

    // zero A slots + h buffers once
    {
        uint4 z = make_uint4(0, 0, 0, 0);
        uint4* sA = (uint4*)(smc + A_OFF);
        for (int i = tid; i < (2 * A_SLOT) / 16; i += 192) sA[i] = z;
        if (tid < 16) ((uint4*)(smc + HB_OFF))[tid] = z;   // 256 B of h state
    }

    // ---- producer setup: prologue cp.async FIRST, then gather B fragments ----
    uint32_t bf[NKT][2][2];
    if (!is_rec) {
        const float4* src = (const float4*)(x +
            ((size_t)(b0 + bt) * SEQ + nh * 16) * EMB);
        uint32_t dst = sbase + X32_OFF + (bt * 2 + 0) * X32_SLOT + nh * 16 * 1200;
        for (int i = lane; i < 1200; i += 32) cpa16(dst + i * 16, src + i);
        cpa_commit();

        // fused prep: W_ih_f -> fp16 B fragments (rows<20 pre-scaled 0.5)
        const int n = nh * 16 + (lane >> 2);         // + nt*8
        const int kbase = (lane & 3) * 2;            // + kt*16 + j*8
#pragma unroll
        for (int kt = 0; kt < NKT; ++kt)
#pragma unroll
            for (int nt = 0; nt < 2; ++nt)
#pragma unroll
                for (int j = 0; j < 2; ++j) {
                    int nn = n + nt * 8;
                    int kk = kt * 16 + kbase + j * 8;
                    float sc = (nn < 20) ? 0.5f : 1.0f;
                    float w0 = (nn < G3 && kk < EMB)
                             ? sc * __ldg(w_ihf + nn * EMB + kk) : 0.0f;
                    float w1 = (nn < G3 && kk + 1 < EMB)
                             ? sc * __ldg(w_ihf + nn * EMB + kk + 1) : 0.0f;
                    __half2 hh = __floats2half2_rn(w0, w1);
                    bf[kt][nt][j] = *(uint32_t*)&hh;
                }
    }

    // ---- rec setup: per-j f32x2 gate rows + biases + bwd-dir gi dot ----
    const int l   = lane;
    const int l30 = (l < G3) ? l : 0;
    const int j10 = (l < HID) ? l : 0;
    float gb = 0.0f;
    unsigned long long wr2[5], wz2[5], wn2[5], hbnp = 0ULL;
    float cbr = 0.0f, cbz = 0.0f, bin_ = 0.0f;
    float hj = 0.0f;

    if (is_rec) {
        const int b = b0 + bt;
        const float4* xq = (const float4*)(x + ((size_t)b * SEQ + SEQ - 1) * EMB);
        const float4* wq = (const float4*)(w_ihb + (size_t)l30 * EMB);
        float a0 = 0, a1 = 0, a2 = 0, a3 = 0;
#pragma unroll 5
        for (int k4 = 0; k4 < EMB / 4; ++k4) {
            float4 xv = __ldg(xq + k4);
            float4 wv4 = __ldg(wq + k4);
            a0 = fmaf(xv.x, wv4.x, a0);
            a1 = fmaf(xv.y, wv4.y, a1);
            a2 = fmaf(xv.z, wv4.z, a2);
            a3 = fmaf(xv.w, wv4.w, a3);
        }
        gb = (a0 + a1) + (a2 + a3) + ((l < G3) ? __ldg(b_ihb + l) : 0.0f);

#pragma unroll
        for (int k = 0; k < 5; ++k) { wr2[k] = 0; wz2[k] = 0; wn2[k] = 0; }
        if (l < HID) {
#pragma unroll
            for (int k = 0; k < 5; ++k) {
                wr2[k] = pk2(0.5f * __ldg(whh + l * HID + 2 * k),
                             0.5f * __ldg(whh + l * HID + 2 * k + 1));
                wz2[k] = pk2(0.5f * __ldg(whh + (l + 10) * HID + 2 * k),
                             0.5f * __ldg(whh + (l + 10) * HID + 2 * k + 1));
                wn2[k] = pk2(0.5f * __ldg(whh + (l + 20) * HID + 2 * k),
                             0.5f * __ldg(whh + (l + 20) * HID + 2 * k + 1));
            }
            cbr  = 0.5f * (__ldg(b_ihf + l)      + __ldg(bhhf + l));
            cbz  = 0.5f * (__ldg(b_ihf + l + 10) + __ldg(bhhf + l + 10));
            bin_ = __ldg(b_ihf + l + 20);
            hbnp = pk2(0.5f * __ldg(bhhf + l + 20), 0.0f);
        }
    }

    __syncthreads();

    // ---- lockstep: cpasync(p+1) | convert(p)+HMMA(p) | consume(p-1) ----
    for (int p = 0; p <= NCH; ++p) {
        if (!is_rec) {
            if (p + 1 < NCH) {
                const float4* src = (const float4*)(x +
                    ((size_t)(b0 + bt) * SEQ + (size_t)(p + 1) * CHUNK + nh * 16) * EMB);
                uint32_t dst = sbase + X32_OFF
                    + (bt * 2 + ((p + 1) & 1)) * X32_SLOT + nh * 16 * 1200;
                for (int i = lane; i < 1200; i += 32) cpa16(dst + i * 16, src + i);
                cpa_commit();
            }

            if (p < NCH) {
                if (p + 1 < NCH) cpa_wait1(); else cpa_wait0();

                const float4* xs = (const float4*)(smc + X32_OFF
                    + (bt * 2 + (p & 1)) * X32_SLOT + nh * 16 * 1200);
                char* aslot = smc + A_OFF + bt * A_SLOT;
#pragma unroll 4
                for (int i = lane; i < 16 * 75; i += 32) {
                    int row = i / 75, q = i - row * 75;
                    float4 v = xs[i];
                    __half2 h0 = __floats2half2_rn(v.x, v.y);
                    __half2 h1 = __floats2half2_rn(v.z, v.w);
                    *(uint2*)(aslot + (nh * 16 + row) * A_STRIDE + q * 8) =
                        make_uint2(*(uint32_t*)&h0, *(uint32_t*)&h1);
                }

                asm volatile("bar.sync %0, 64;" :: "r"(1 + bt) : "memory");

                const uint32_t abase = sbase + A_OFF + bt * A_SLOT;
                float* gis = (float*)(smc + GI_OFF + (bt * 2 + (p & 1)) * GI_SLOT);
                const int mi = lane >> 3, r = lane & 7;

                float d[2][2][4];
#pragma unroll
                for (int mt = 0; mt < 2; ++mt)
#pragma unroll
                    for (int nt = 0; nt < 2; ++nt)
#pragma unroll
                        for (int e = 0; e < 4; ++e) d[mt][nt][e] = 0.0f;

#pragma unroll
                for (int kt = 0; kt < NKT; ++kt) {
#pragma unroll
                    for (int mt = 0; mt < 2; ++mt) {
                        uint32_t addr = abase
                            + (mt * 16 + (mi & 1) * 8 + r) * A_STRIDE
                            + (mi >> 1) * 16 + kt * 32;
                        uint32_t a0, a1, a2, a3;
                        ldsm4(a0, a1, a2, a3, addr);
                        mma16816(d[mt][0], a0, a1, a2, a3,
                                 bf[kt][0][0], bf[kt][0][1]);
                        mma16816(d[mt][1], a0, a1, a2, a3,
                                 bf[kt][1][0], bf[kt][1][1]);
                    }
                }

                // TRANSPOSED store: gi[gate][step], stride 36 floats
                const int rq = lane >> 2, cq = (lane & 3) * 2;
#pragma unroll
                for (int mt = 0; mt < 2; ++mt)
#pragma unroll
                    for (int nt = 0; nt < 2; ++nt) {
                        int col = nh * 16 + nt * 8 + cq;   // gate
                        int row = mt * 16 + rq;            // step
                        gis[col * GIT_STRIDE + row]           = d[mt][nt][0];
                        gis[(col + 1) * GIT_STRIDE + row]     = d[mt][nt][1];
                        gis[col * GIT_STRIDE + row + 8]       = d[mt][nt][2];
                        gis[(col + 1) * GIT_STRIDE + row + 8] = d[mt][nt][3];
                    }
            }
        }

        // consumer: chunk p-1 — per-j, SMEM-h double buffer, NO syncwarp
        if (is_rec && p >= 1) {
            const int c = p - 1;
            const float* gis =
                (const float*)(smc + GI_OFF + (bt * 2 + (c & 1)) * GI_SLOT);
            const float4* rq4 = (const float4*)(gis + j10 * GIT_STRIDE);
            const float4* zq4 = (const float4*)(gis + (j10 + 10) * GIT_STRIDE);
            const float4* nq4 = (const float4*)(gis + (j10 + 20) * GIT_STRIDE);
            const uint32_t hb0 = sbase + HB_OFF + bt * 128;        // parity 0
            const uint32_t hb1 = hb0 + 64;                         // parity 1
            const uint32_t hst0 = hb0 + j10 * 4;                   // store addrs
            const uint32_t hst1 = hb1 + j10 * 4;

            float4 r4 = rq4[0], z4 = zq4[0], n4 = nq4[0];
#pragma unroll 1
            for (int q = 0; q < 8; ++q) {
                int qn = (q + 1) & 7;
                float4 r4n = rq4[qn], z4n = zq4[qn], n4n = nq4[qn];
#pragma unroll
                for (int u4 = 0; u4 < 4; ++u4) {
                    const uint32_t ha = (u4 & 1) ? hb1 : hb0;

                    // read h via explicit asm (ordered after last step's STS)
                    unsigned long long hx, hy, hz, hw, h4;
                    asm volatile("ld.shared.v2.u64 {%0,%1}, [%2];"
                                 : "=l"(hx), "=l"(hy) : "r"(ha) : "memory");
                    asm volatile("ld.shared.v2.u64 {%0,%1}, [%2];"
                                 : "=l"(hz), "=l"(hw) : "r"(ha + 16) : "memory");
                    asm volatile("ld.shared.u64 %0, [%1];"
                                 : "=l"(h4) : "r"(ha + 32) : "memory");

                    float grp = getc(r4, u4) + cbr;
                    float gzp = getc(z4, u4) + cbz;
                    float gnp = getc(n4, u4) + bin_;

                    unsigned long long aR = fma2(hx, wr2[0], pk2(grp, 0.0f));
                    unsigned long long bR = fma2(hy, wr2[1], 0ULL);
                    unsigned long long aZ = fma2(hx, wz2[0], pk2(gzp, 0.0f));
                    unsigned long long bZ = fma2(hy, wz2[1], 0ULL);
                    unsigned long long aN = fma2(hx, wn2[0], hbnp);
                    unsigned long long bN = fma2(hy, wn2[1], 0ULL);
                    aR = fma2(hz, wr2[2], aR);  bR = fma2(hw, wr2[3], bR);
                    aZ = fma2(hz, wz2[2], aZ);  bZ = fma2(hw, wz2[3], bZ);
                    aN = fma2(hz, wn2[2], aN);  bN = fma2(hw, wn2[3], bN);
                    aR = fma2(h4, wr2[4], aR);
                    aZ = fma2(h4, wz2[4], aZ);
                    aN = fma2(h4, wn2[4], aN);

                    float x0, x1;
                    upk2(add2(aR, bR), x0, x1);
                    float ar = x0 + x1;
                    upk2(add2(aZ, bZ), x0, x1);
                    float az = x0 + x1;
                    upk2(add2(aN, bN), x0, x1);
                    float ah = x0 + x1;

                    float tr = tanha(ar);
                    float tz = tanha(az);
                    float nn = tanha(fmaf(ah, tr, gnp + ah));
                    float z  = fmaf(tz, 0.5f, 0.5f);
                    hj = fmaf(z, hj - nn, nn);

                    // write next-parity h (predicated @P STS, warp stays convergent)
                    const uint32_t hs = (u4 & 1) ? hst0 : hst1;
                    if (l < HID)
                        asm volatile("st.shared.f32 [%0], %1;"
                                     :: "r"(hs), "f"(hj) : "memory");
                }
                r4 = r4n; z4 = z4n; n4 = n4n;
            }
        }

        __syncthreads();
    }

    // ---- epilogue: backward single step + linear head ----
    if (is_rec) {
        float bb  = (l < G3) ? __ldg(bhhb + l) : 0.0f;
        float sb  = gb + bb;
        float azb = __shfl_sync(mfull, sb, l + 10);
        float gbn = __shfl_sync(mfull, gb, l + 20);
        float bbn = __shfl_sync(mfull, bb, l + 20);
        float rb  = sig_full(sb);
        float zb  = sig_full(azb);
        float nb  = tanha(fmaf(rb, bbn, gbn));
        float hbv = (1.0f - zb) * nb;

        float cacc = 0.0f;
        if (l < HID) cacc = __ldg(wlin + l) * hj + __ldg(wlin + HID + l) * hbv;
        cacc += __shfl_down_sync(mfull, cacc, 8);
        cacc += __shfl_down_sync(mfull, cacc, 4);
        cacc += __shfl_down_sync(mfull, cacc, 2);
        cacc += __shfl_down_sync(mfull, cacc, 1);
        if (l == 0) out[b0 + bt] = cacc + __ldg(blin);
    }
}

extern "C" void kernel_launch(void* const* d_in, const int* in_sizes, int n_in,
                              void* d_out, int out_size)
{
    const float* x      = (const float*)d_in[0];
    const float* w_ih_f = (const float*)d_in[1];
    const float* w_hh_f = (const float*)d_in[2];
    const float* b_ih_f = (const float*)d_in[3];
    const float* b_hh_f = (const float*)d_in[4];
    const float* w_ih_b = (const float*)d_in[5];
    /* w_hh_b (d_in[6]) mathematically unused: h0 = 0 for the single bwd step */
    const float* b_ih_b = (const float*)d_in[7];
    const float* b_hh_b = (const float*)d_in[8];
    const float* w_lin  = (const float*)d_in[9];
    const float* b_lin  = (const float*)d_in[10];
    float* out = (float*)d_out;

    cudaFuncSetAttribute(k_fused, cudaFuncAttributeMaxDynamicSharedMemorySize,
                         SMEM_B);
    k_fused<<<BATCH / 2, 192, SMEM_B>>>(x, w_ih_f, b_ih_f, w_ih_b, b_ih_b,
                                        w_hh_f, b_hh_f, b_hh_b, w_lin, b_lin,
                                        out);
}

// round 17
// speedup vs baseline: 1.1068x; 1.0043x over previous
#include <cuda_runtime.h>
#include <cuda_fp16.h>
#include <cstdint>

#define SEQ 512
#define BATCH 256
#define EMB 300
#define HID 10
#define G3 30
#define CHUNK 32
#define NCH 16
#define NKT 19                  // k-tiles of 16: covers k 0..303

// SMEM layout (bytes)
#define X32_OFF  0
#define X32_SLOT 38400          // 32 rows x 300 fp32; slots: (bt*2 + parity)
#define A_STRIDE 656            // 328 halves/row (304 used + pad), LDSM-friendly
#define A_SLOT   (32 * A_STRIDE)              // 20992; one per bt
#define A_OFF    (4 * X32_SLOT)               // 153600
// gi tile TRANSPOSED: [gate 0..31][step 0..31], stride 36 floats (16B-aligned)
#define GIT_STRIDE 36
#define GI_SLOT  (32 * GIT_STRIDE * 4)        // 4608
#define GI_OFF   (A_OFF + 2 * A_SLOT)         // 195584
// h state: per bt, 2 buffers x 16 floats (double-buffered by step parity)
#define HB_OFF   (GI_OFF + 4 * GI_SLOT)       // 214016
#define SMEM_B   (HB_OFF + 256)               // 214272

// ---------- helpers ----------
__device__ __forceinline__ float tanha(float x) {
    float y;
    asm("tanh.approx.f32 %0, %1;" : "=f"(y) : "f"(x));
    return y;
}
__device__ __forceinline__ float sig_full(float x) {
    return fmaf(tanha(0.5f * x), 0.5f, 0.5f);
}
__device__ __forceinline__ uint32_t s2u(const void* p) {
    uint32_t a;
    asm("{ .reg .u64 t; cvta.to.shared.u64 t, %1; cvt.u32.u64 %0, t; }"
        : "=r"(a) : "l"(p));
    return a;
}
__device__ __forceinline__ unsigned long long pk2(float lo, float hi) {
    unsigned long long r;
    asm("mov.b64 %0, {%1, %2};" : "=l"(r) : "f"(lo), "f"(hi));
    return r;
}
__device__ __forceinline__ void upk2(unsigned long long v, float& lo, float& hi) {
    asm("mov.b64 {%0, %1}, %2;" : "=f"(lo), "=f"(hi) : "l"(v));
}
__device__ __forceinline__ unsigned long long fma2(unsigned long long a,
                                                   unsigned long long b,
                                                   unsigned long long c) {
    unsigned long long d;
    asm("fma.rn.f32x2 %0, %1, %2, %3;" : "=l"(d) : "l"(a), "l"(b), "l"(c));
    return d;
}
__device__ __forceinline__ unsigned long long add2(unsigned long long a,
                                                   unsigned long long b) {
    unsigned long long d;
    asm("add.rn.f32x2 %0, %1, %2;" : "=l"(d) : "l"(a), "l"(b));
    return d;
}
__device__ __forceinline__ float getc(float4 v, int i) {
    return i == 0 ? v.x : i == 1 ? v.y : i == 2 ? v.z : v.w;
}
__device__ __forceinline__ void cpa16(uint32_t dst, const void* src) {
    asm volatile("cp.async.cg.shared.global [%0], [%1], 16;"
                 :: "r"(dst), "l"(src) : "memory");
}
__device__ __forceinline__ void cpa_commit() {
    asm volatile("cp.async.commit_group;" ::: "memory");
}
__device__ __forceinline__ void cpa_wait1() {
    asm volatile("cp.async.wait_group 1;" ::: "memory");
}
__device__ __forceinline__ void cpa_wait0() {
    asm volatile("cp.async.wait_group 0;" ::: "memory");
}
__device__ __forceinline__ void ldsm4(uint32_t& a0, uint32_t& a1,
                                      uint32_t& a2, uint32_t& a3, uint32_t addr) {
    asm volatile("ldmatrix.sync.aligned.m8n8.x4.shared.b16 {%0,%1,%2,%3}, [%4];"
                 : "=r"(a0), "=r"(a1), "=r"(a2), "=r"(a3) : "r"(addr));
}
__device__ __forceinline__ void mma16816(float* d, uint32_t a0, uint32_t a1,
                                         uint32_t a2, uint32_t a3,
                                         uint32_t b0, uint32_t b1) {
    asm volatile(
        "mma.sync.aligned.m16n8k16.row.col.f32.f16.f16.f32 "
        "{%0,%1,%2,%3}, {%4,%5,%6,%7}, {%8,%9}, {%0,%1,%2,%3};"
        : "+f"(d[0]), "+f"(d[1]), "+f"(d[2]), "+f"(d[3])
        : "r"(a0), "r"(a1), "r"(a2), "r"(a3), "r"(b0), "r"(b1));
}

// ---------- fused kernel: 192 threads (6 warps), 1 block = 2 batches -------
// wid 0,1: producers bt0 | wid 4,5: producers bt1
// wid 2: rec bt0 | wid 3: rec bt1  (each rec warp alone on SMSP 2 / 3)
// Per-bt named barriers (96 threads) decouple the two batches' pipelines.
__global__ void __launch_bounds__(192, 1) k_fused(
    const float* __restrict__ x,
    const float* __restrict__ w_ihf, const float* __restrict__ b_ihf,
    const float* __restrict__ w_ihb, const float* __restrict__ b_ihb,
    const float* __restrict__ whh,  const float* __restrict__ bhhf,
    const float* __restrict__ bhhb, const float* __restrict__ wlin,
    const float* __restrict__ blin, float* __restrict__ out)
{
    extern __shared__ char smc[];
    const uint32_t sbase = s2u(smc);
    const int tid  = threadIdx.x;
    const int wid  = tid >> 5;
    const int lane = tid & 31;
    const int b0   = blockIdx.x * 2;
    const unsigned mfull = 0xffffffffu;

    const bool is_rec = (wid == 2) || (wid == 3);
    const int bt = is_rec ? (wid - 2) : ((wid >= 4) ? 1 : 0);
    const int nh = wid & 1;

    // zero A slots + h buffers once
    {
        uint4 z = make_uint4(0, 0, 0, 0);
        uint4* sA = (uint4*)(smc + A_OFF);
        for (int i = tid; i < (2 * A_SLOT) / 16; i += 192) sA[i] = z;
        if (tid < 16) ((uint4*)(smc + HB_OFF))[tid] = z;   // 256 B of h state
    }

    // ---- producer setup: prologue cp.async FIRST, then gather B fragments ----
    uint32_t bf[NKT][2][2];
    if (!is_rec) {
        const float4* src = (const float4*)(x +
            ((size_t)(b0 + bt) * SEQ + nh * 16) * EMB);
        uint32_t dst = sbase + X32_OFF + (bt * 2 + 0) * X32_SLOT + nh * 16 * 1200;
        for (int i = lane; i < 1200; i += 32) cpa16(dst + i * 16, src + i);
        cpa_commit();

        // fused prep: W_ih_f -> fp16 B fragments (rows<20 pre-scaled 0.5)
        const int n = nh * 16 + (lane >> 2);
        const int kbase = (lane & 3) * 2;
#pragma unroll
        for (int kt = 0; kt < NKT; ++kt)
#pragma unroll
            for (int nt = 0; nt < 2; ++nt)
#pragma unroll
                for (int j = 0; j < 2; ++j) {
                    int nn = n + nt * 8;
                    int kk = kt * 16 + kbase + j * 8;
                    float sc = (nn < 20) ? 0.5f : 1.0f;
                    float w0 = (nn < G3 && kk < EMB)
                             ? sc * __ldg(w_ihf + nn * EMB + kk) : 0.0f;
                    float w1 = (nn < G3 && kk + 1 < EMB)
                             ? sc * __ldg(w_ihf + nn * EMB + kk + 1) : 0.0f;
                    __half2 hh = __floats2half2_rn(w0, w1);
                    bf[kt][nt][j] = *(uint32_t*)&hh;
                }
    }

    // ---- rec setup: per-j f32x2 gate rows + biases + bwd-dir gi dot ----
    const int l   = lane;
    const int l30 = (l < G3) ? l : 0;
    const int j10 = (l < HID) ? l : 0;
    float gb = 0.0f;
    unsigned long long wr2[5], wz2[5], wn2[5], hbnp = 0ULL;
    float cbr = 0.0f, cbz = 0.0f, bin_ = 0.0f;
    float hj = 0.0f;

    if (is_rec) {
        const int b = b0 + bt;
        const float4* xq = (const float4*)(x + ((size_t)b * SEQ + SEQ - 1) * EMB);
        const float4* wq = (const float4*)(w_ihb + (size_t)l30 * EMB);
        float a0 = 0, a1 = 0, a2 = 0, a3 = 0;
#pragma unroll 5
        for (int k4 = 0; k4 < EMB / 4; ++k4) {
            float4 xv = __ldg(xq + k4);
            float4 wv4 = __ldg(wq + k4);
            a0 = fmaf(xv.x, wv4.x, a0);
            a1 = fmaf(xv.y, wv4.y, a1);
            a2 = fmaf(xv.z, wv4.z, a2);
            a3 = fmaf(xv.w, wv4.w, a3);
        }
        gb = (a0 + a1) + (a2 + a3) + ((l < G3) ? __ldg(b_ihb + l) : 0.0f);

#pragma unroll
        for (int k = 0; k < 5; ++k) { wr2[k] = 0; wz2[k] = 0; wn2[k] = 0; }
        if (l < HID) {
#pragma unroll
            for (int k = 0; k < 5; ++k) {
                wr2[k] = pk2(0.5f * __ldg(whh + l * HID + 2 * k),
                             0.5f * __ldg(whh + l * HID + 2 * k + 1));
                wz2[k] = pk2(0.5f * __ldg(whh + (l + 10) * HID + 2 * k),
                             0.5f * __ldg(whh + (l + 10) * HID + 2 * k + 1));
                wn2[k] = pk2(0.5f * __ldg(whh + (l + 20) * HID + 2 * k),
                             0.5f * __ldg(whh + (l + 20) * HID + 2 * k + 1));
            }
            cbr  = 0.5f * (__ldg(b_ihf + l)      + __ldg(bhhf + l));
            cbz  = 0.5f * (__ldg(b_ihf + l + 10) + __ldg(bhhf + l + 10));
            bin_ = __ldg(b_ihf + l + 20);
            hbnp = pk2(0.5f * __ldg(bhhf + l + 20), 0.0f);
        }
    }

    __syncthreads();

    // ---- lockstep per bt: cpasync(p+1) | convert(p)+HMMA(p) | consume(p-1) --
    for (int p = 0; p <= NCH; ++p) {
        if (!is_rec) {
            if (p + 1 < NCH) {
                const float4* src = (const float4*)(x +
                    ((size_t)(b0 + bt) * SEQ + (size_t)(p + 1) * CHUNK + nh * 16) * EMB);
                uint32_t dst = sbase + X32_OFF
                    + (bt * 2 + ((p + 1) & 1)) * X32_SLOT + nh * 16 * 1200;
                for (int i = lane; i < 1200; i += 32) cpa16(dst + i * 16, src + i);
                cpa_commit();
            }

            if (p < NCH) {
                if (p + 1 < NCH) cpa_wait1(); else cpa_wait0();

                const float4* xs = (const float4*)(smc + X32_OFF
                    + (bt * 2 + (p & 1)) * X32_SLOT + nh * 16 * 1200);
                char* aslot = smc + A_OFF + bt * A_SLOT;
#pragma unroll 4
                for (int i = lane; i < 16 * 75; i += 32) {
                    int row = i / 75, q = i - row * 75;
                    float4 v = xs[i];
                    __half2 h0 = __floats2half2_rn(v.x, v.y);
                    __half2 h1 = __floats2half2_rn(v.z, v.w);
                    *(uint2*)(aslot + (nh * 16 + row) * A_STRIDE + q * 8) =
                        make_uint2(*(uint32_t*)&h0, *(uint32_t*)&h1);
                }

                asm volatile("bar.sync %0, 64;" :: "r"(1 + bt) : "memory");

                const uint32_t abase = sbase + A_OFF + bt * A_SLOT;
                float* gis = (float*)(smc + GI_OFF + (bt * 2 + (p & 1)) * GI_SLOT);
                const int mi = lane >> 3, r = lane & 7;

                float d[2][2][4];
#pragma unroll
                for (int mt = 0; mt < 2; ++mt)
#pragma unroll
                    for (int nt = 0; nt < 2; ++nt)
#pragma unroll
                        for (int e = 0; e < 4; ++e) d[mt][nt][e] = 0.0f;

#pragma unroll
                for (int kt = 0; kt < NKT; ++kt) {
#pragma unroll
                    for (int mt = 0; mt < 2; ++mt) {
                        uint32_t addr = abase
                            + (mt * 16 + (mi & 1) * 8 + r) * A_STRIDE
                            + (mi >> 1) * 16 + kt * 32;
                        uint32_t a0, a1, a2, a3;
                        ldsm4(a0, a1, a2, a3, addr);
                        mma16816(d[mt][0], a0, a1, a2, a3,
                                 bf[kt][0][0], bf[kt][0][1]);
                        mma16816(d[mt][1], a0, a1, a2, a3,
                                 bf[kt][1][0], bf[kt][1][1]);
                    }
                }

                // TRANSPOSED store: gi[gate][step], stride 36 floats
                const int rq = lane >> 2, cq = (lane & 3) * 2;
#pragma unroll
                for (int mt = 0; mt < 2; ++mt)
#pragma unroll
                    for (int nt = 0; nt < 2; ++nt) {
                        int col = nh * 16 + nt * 8 + cq;   // gate
                        int row = mt * 16 + rq;            // step
                        gis[col * GIT_STRIDE + row]           = d[mt][nt][0];
                        gis[(col + 1) * GIT_STRIDE + row]     = d[mt][nt][1];
                        gis[col * GIT_STRIDE + row + 8]       = d[mt][nt][2];
                        gis[(col + 1) * GIT_STRIDE + row + 8] = d[mt][nt][3];
                    }
            }
        }

        // consumer: chunk p-1 — per-j, SMEM-h, fully unrolled 32 steps
        if (is_rec && p >= 1) {
            const int c = p - 1;
            const float* gis =
                (const float*)(smc + GI_OFF + (bt * 2 + (c & 1)) * GI_SLOT);
            const float4* rq4 = (const float4*)(gis + j10 * GIT_STRIDE);
            const float4* zq4 = (const float4*)(gis + (j10 + 10) * GIT_STRIDE);
            const float4* nq4 = (const float4*)(gis + (j10 + 20) * GIT_STRIDE);
            const uint32_t hb0 = sbase + HB_OFF + bt * 128;
            const uint32_t hb1 = hb0 + 64;
            const uint32_t hst0 = hb0 + j10 * 4;
            const uint32_t hst1 = hb1 + j10 * 4;

#pragma unroll
            for (int q = 0; q < 8; ++q) {
                float4 r4 = rq4[q], z4 = zq4[q], n4 = nq4[q];
#pragma unroll
                for (int u4 = 0; u4 < 4; ++u4) {
                    const uint32_t ha = (u4 & 1) ? hb1 : hb0;

                    // h load: volatile (ordered vs the volatile STS below),
                    // NO memory clobber -> gi loads may be hoisted across
                    unsigned long long hx, hy, hz, hw, h4;
                    asm volatile("ld.shared.v2.u64 {%0,%1}, [%2];"
                                 : "=l"(hx), "=l"(hy) : "r"(ha));
                    asm volatile("ld.shared.v2.u64 {%0,%1}, [%2];"
                                 : "=l"(hz), "=l"(hw) : "r"(ha + 16));
                    asm volatile("ld.shared.u64 %0, [%1];"
                                 : "=l"(h4) : "r"(ha + 32));

                    float grp = getc(r4, u4) + cbr;
                    float gzp = getc(z4, u4) + cbz;
                    float gnp = getc(n4, u4) + bin_;

                    unsigned long long aR = fma2(hx, wr2[0], pk2(grp, 0.0f));
                    unsigned long long bR = fma2(hy, wr2[1], 0ULL);
                    unsigned long long aZ = fma2(hx, wz2[0], pk2(gzp, 0.0f));
                    unsigned long long bZ = fma2(hy, wz2[1], 0ULL);
                    unsigned long long aN = fma2(hx, wn2[0], hbnp);
                    unsigned long long bN = fma2(hy, wn2[1], 0ULL);
                    aR = fma2(hz, wr2[2], aR);  bR = fma2(hw, wr2[3], bR);
                    aZ = fma2(hz, wz2[2], aZ);  bZ = fma2(hw, wz2[3], bZ);
                    aN = fma2(hz, wn2[2], aN);  bN = fma2(hw, wn2[3], bN);
                    aR = fma2(h4, wr2[4], aR);
                    aZ = fma2(h4, wz2[4], aZ);
                    aN = fma2(h4, wn2[4], aN);

                    float x0, x1;
                    upk2(add2(aR, bR), x0, x1);
                    float ar = x0 + x1;
                    upk2(add2(aZ, bZ), x0, x1);
                    float az = x0 + x1;
                    upk2(add2(aN, bN), x0, x1);
                    float ah = x0 + x1;

                    float tr = tanha(ar);
                    float tz = tanha(az);
                    float nn = tanha(fmaf(ah, tr, gnp + ah));
                    float z  = fmaf(tz, 0.5f, 0.5f);
                    hj = fmaf(z, hj - nn, nn);

                    const uint32_t hs = (u4 & 1) ? hst0 : hst1;
                    if (l < HID)
                        asm volatile("st.shared.f32 [%0], %1;"
                                     :: "r"(hs), "f"(hj));
                }
            }
        }

        // per-bt phase barrier: 2 producers + 1 rec = 96 threads
        asm volatile("bar.sync %0, 96;" :: "r"(5 + bt) : "memory");
    }

    // ---- epilogue: backward single step + linear head ----
    if (is_rec) {
        float bb  = (l < G3) ? __ldg(bhhb + l) : 0.0f;
        float sb  = gb + bb;
        float azb = __shfl_sync(mfull, sb, l + 10);
        float gbn = __shfl_sync(mfull, gb, l + 20);
        float bbn = __shfl_sync(mfull, bb, l + 20);
        float rb  = sig_full(sb);
        float zb  = sig_full(azb);
        float nb  = tanha(fmaf(rb, bbn, gbn));
        float hbv = (1.0f - zb) * nb;

        float cacc = 0.0f;
        if (l < HID) cacc = __ldg(wlin + l) * hj + __ldg(wlin + HID + l) * hbv;
        cacc += __shfl_down_sync(mfull, cacc, 8);
        cacc += __shfl_down_sync(mfull, cacc, 4);
        cacc += __shfl_down_sync(mfull, cacc, 2);
        cacc += __shfl_down_sync(mfull, cacc, 1);
        if (l == 0) out[b0 + bt] = cacc + __ldg(blin);
    }
}

extern "C" void kernel_launch(void* const* d_in, const int* in_sizes, int n_in,
                              void* d_out, int out_size)
{
    const float* x      = (const float*)d_in[0];
    const float* w_ih_f = (const float*)d_in[1];
    const float* w_hh_f = (const float*)d_in[2];
    const float* b_ih_f = (const float*)d_in[3];
    const float* b_hh_f = (const float*)d_in[4];
    const float* w_ih_b = (const float*)d_in[5];
    /* w_hh_b (d_in[6]) mathematically unused: h0 = 0 for the single bwd step */
    const float* b_ih_b = (const float*)d_in[7];
    const float* b_hh_b = (const float*)d_in[8];
    const float* w_lin  = (const float*)d_in[9];
    const float* b_lin  = (const float*)d_in[10];
    float* out = (float*)d_out;

    cudaFuncSetAttribute(k_fused, cudaFuncAttributeMaxDynamicSharedMemorySize,
                         SMEM_B);
    k_fused<<<BATCH / 2, 192, SMEM_B>>>(x, w_ih_f, b_ih_f, w_ih_b, b_ih_b,
                                        w_hh_f, b_hh_f, b_hh_b, w_lin, b_lin,
                                        out);
}